// round 3
// baseline (speedup 1.0000x reference)
#include <cuda_runtime.h>

#define NN 100000
#define NE 1600000
#define D  128

// ---------------- scratch (device globals — no allocation allowed) ----------
__device__ __align__(16) int   g_cursor[NN];
__device__ __align__(16) int   g_rowptr[NN + 1];
__device__ __align__(16) int   g_col[NE];
__device__ __align__(16) float g_agg[(size_t)NN * D];
__device__ __align__(16) float g_h1 [(size_t)NN * D];
__device__ __align__(16) float g_h2 [(size_t)NN * D];

// ---------------- CSR build --------------------------------------------------
__global__ void zero_cursor_kernel() {
    int i = blockIdx.x * blockDim.x + threadIdx.x;
    if (i < NN) g_cursor[i] = 0;
}

// edge_index is int32 on device (JAX default x64-disabled downcasts int64->int32).
__global__ void hist_kernel(const int* __restrict__ ei) {
    int e = blockIdx.x * blockDim.x + threadIdx.x;
    if (e < NE) {
        int dst = ei[NE + e];
        if ((unsigned)dst < NN) atomicAdd(&g_cursor[dst], 1);
    }
}

// single-block exclusive scan over NN counts -> g_rowptr
__global__ void scan_kernel() {
    __shared__ int s[1024];
    __shared__ int carry;
    int tid = threadIdx.x;
    if (tid == 0) carry = 0;
    __syncthreads();
    for (int base = 0; base < NN; base += 1024) {
        int i = base + tid;
        int v = (i < NN) ? g_cursor[i] : 0;
        s[tid] = v;
        __syncthreads();
        #pragma unroll
        for (int off = 1; off < 1024; off <<= 1) {
            int t = (tid >= off) ? s[tid - off] : 0;
            __syncthreads();
            s[tid] += t;
            __syncthreads();
        }
        int incl = s[tid];
        int c = carry;
        if (i < NN) g_rowptr[i] = c + incl - v;   // exclusive
        __syncthreads();
        if (tid == 1023) carry = c + incl;
        __syncthreads();
    }
    if (tid == 0) g_rowptr[NN] = carry;
}

__global__ void fill_kernel(const int* __restrict__ ei) {
    int e = blockIdx.x * blockDim.x + threadIdx.x;
    if (e < NE) {
        int src = ei[e];
        int dst = ei[NE + e];
        if ((unsigned)dst < NN && (unsigned)src < NN) {
            int pos = atomicAdd(&g_cursor[dst], 1);
            g_col[g_rowptr[dst] + pos] = src;
        }
    }
}

// ---------------- aggregation: one warp per node, float4 lanes ---------------
// which: 0 -> read from x (arg), 1 -> g_h1, 2 -> g_h2. Output always g_agg.
__global__ void agg_kernel(const float* __restrict__ xin, int which) {
    int gw   = (blockIdx.x * blockDim.x + threadIdx.x) >> 5;
    int lane = threadIdx.x & 31;
    if (gw >= NN) return;
    const float* h = (which == 0) ? xin : (which == 1 ? g_h1 : g_h2);
    int beg = g_rowptr[gw];
    int end = g_rowptr[gw + 1];
    const float4* hv = (const float4*)h;
    float4 acc = make_float4(0.f, 0.f, 0.f, 0.f);
    for (int j = beg; j < end; j++) {
        int s = g_col[j];
        float4 v = hv[(size_t)s * 32 + lane];
        acc.x += v.x; acc.y += v.y; acc.z += v.z; acc.w += v.w;
    }
    ((float4*)g_agg)[(size_t)gw * 32 + lane] = acc;
}

// ---------------- fused GEMM: out = act([g_agg | h] @ [Wrel;Wroot] + b) ------
// BM=128, BN=128, BK=8, 256 threads, 8x8 register tile per thread.
template <bool RELU>
__global__ void __launch_bounds__(256, 2)
gemm_fused_kernel(const float* __restrict__ xin,  int which,
                  const float* __restrict__ W0,   // w_rel  (128 x 128)
                  const float* __restrict__ W1,   // w_root (128 x 128)
                  const float* __restrict__ bias, // (128)
                  float* __restrict__ outarg, int outsel)
{
    __shared__ float As[8][128];
    __shared__ float Bs[8][128];

    const float* A1  = (which == 0) ? xin : (which == 1 ? g_h1 : g_h2);
    float*       out = (outsel == 0) ? g_h1 : (outsel == 1 ? g_h2 : outarg);

    const int tid = threadIdx.x;
    const int m0  = blockIdx.x * 128;
    const int tx  = tid & 15;       // 0..15  -> n
    const int ty  = tid >> 4;       // 0..15  -> m

    const int ar = tid >> 1;          // 0..127
    const int ak = (tid & 1) * 4;     // 0 or 4
    const int br = tid >> 5;          // 0..7
    const int bc = (tid & 31) * 4;    // 0..124

    float acc[8][8];
    #pragma unroll
    for (int i = 0; i < 8; i++)
        #pragma unroll
        for (int j = 0; j < 8; j++) acc[i][j] = 0.f;

    #pragma unroll 1
    for (int kt = 0; kt < 32; kt++) {
        const float* A = (kt < 16) ? g_agg : A1;
        const float* W = (kt < 16) ? W0 : W1;
        const int kcol = (kt & 15) * 8;

        // stage A (transposed: As[k][m])
        {
            int row = m0 + ar;
            float4 av = make_float4(0.f, 0.f, 0.f, 0.f);
            if (row < NN)
                av = *(const float4*)&A[(size_t)row * 128 + kcol + ak];
            As[ak + 0][ar] = av.x;
            As[ak + 1][ar] = av.y;
            As[ak + 2][ar] = av.z;
            As[ak + 3][ar] = av.w;
        }
        // stage B
        {
            float4 bv = *(const float4*)&W[(size_t)(kcol + br) * 128 + bc];
            *(float4*)&Bs[br][bc] = bv;
        }
        __syncthreads();

        #pragma unroll
        for (int kk = 0; kk < 8; kk++) {
            float a[8], b[8];
            *(float4*)&a[0] = *(const float4*)&As[kk][ty * 8];
            *(float4*)&a[4] = *(const float4*)&As[kk][ty * 8 + 4];
            *(float4*)&b[0] = *(const float4*)&Bs[kk][tx * 8];
            *(float4*)&b[4] = *(const float4*)&Bs[kk][tx * 8 + 4];
            #pragma unroll
            for (int i = 0; i < 8; i++)
                #pragma unroll
                for (int j = 0; j < 8; j++)
                    acc[i][j] += a[i] * b[j];
        }
        __syncthreads();
    }

    // epilogue: bias + optional relu
    #pragma unroll
    for (int i = 0; i < 8; i++) {
        int row = m0 + ty * 8 + i;
        if (row >= NN) continue;
        #pragma unroll
        for (int j = 0; j < 8; j += 4) {
            int col = tx * 8 + j;
            float4 o;
            o.x = acc[i][j + 0] + bias[col + 0];
            o.y = acc[i][j + 1] + bias[col + 1];
            o.z = acc[i][j + 2] + bias[col + 2];
            o.w = acc[i][j + 3] + bias[col + 3];
            if (RELU) {
                o.x = fmaxf(o.x, 0.f);
                o.y = fmaxf(o.y, 0.f);
                o.z = fmaxf(o.z, 0.f);
                o.w = fmaxf(o.w, 0.f);
            }
            *(float4*)&out[(size_t)row * 128 + col] = o;
        }
    }
}

// ---------------- launch ------------------------------------------------------
extern "C" void kernel_launch(void* const* d_in, const int* in_sizes, int n_in,
                              void* d_out, int out_size) {
    const float* x       = (const float*)d_in[0];
    const int*   ei      = (const int*)d_in[1];     // int32 edge_index (2 x NE)
    const float* w_rel1  = (const float*)d_in[2];
    const float* w_root1 = (const float*)d_in[3];
    const float* b1      = (const float*)d_in[4];
    const float* w_rel2  = (const float*)d_in[5];
    const float* w_root2 = (const float*)d_in[6];
    const float* b2      = (const float*)d_in[7];
    const float* w_rel3  = (const float*)d_in[8];
    const float* w_root3 = (const float*)d_in[9];
    const float* b3      = (const float*)d_in[10];
    float*       out     = (float*)d_out;

    const int ZB = (NN + 255) / 256;           // 391
    const int EB = (NE + 255) / 256;           // 6250
    const int AB = ((NN * 32) + 255) / 256;    // 12500 (warp per node)
    const int GB = (NN + 127) / 128;           // 782

    // CSR build (fixed edge list, rebuilt each call for determinism of work)
    zero_cursor_kernel<<<ZB, 256>>>();
    hist_kernel<<<EB, 256>>>(ei);
    scan_kernel<<<1, 1024>>>();
    zero_cursor_kernel<<<ZB, 256>>>();
    fill_kernel<<<EB, 256>>>(ei);

    // layer 1: agg(x) ; h1 = relu([agg|x]W + b1)
    agg_kernel<<<AB, 256>>>(x, 0);
    gemm_fused_kernel<true><<<GB, 256>>>(x, 0, w_rel1, w_root1, b1, nullptr, 0);
    // layer 2
    agg_kernel<<<AB, 256>>>(x, 1);
    gemm_fused_kernel<true><<<GB, 256>>>(x, 1, w_rel2, w_root2, b2, nullptr, 1);
    // layer 3 (no relu) -> d_out
    agg_kernel<<<AB, 256>>>(x, 2);
    gemm_fused_kernel<false><<<GB, 256>>>(x, 2, w_rel3, w_root3, b3, out, 2);
}

// round 5
// speedup vs baseline: 1.5548x; 1.5548x over previous
#include <cuda_runtime.h>
#include <cstdint>

#define NN 100000
#define NE 1600000
#define D  128

// ---------------- scratch (device globals — no allocation allowed) ----------
__device__ __align__(16) int   g_cursor[NN];
__device__ __align__(16) int   g_rowptr[NN + 1];
__device__ __align__(16) int   g_col[NE];
__device__ __align__(16) float g_agg[(size_t)NN * D];
__device__ __align__(16) float g_h1 [(size_t)NN * D];
__device__ __align__(16) float g_h2 [(size_t)NN * D];
// pre-transposed tf32-rounded weights: WT[layer][n=128][k=256] = [w_rel;w_root]^T
__device__ __align__(16) float g_wt [3 * 128 * 256];

__device__ __forceinline__ float tf32_rna(float x) {
    float r; asm("cvt.rna.tf32.f32 %0, %1;" : "=f"(r) : "f"(x)); return r;
}

// warp-level tensor-core mma (baseline PTX, works on compute_103)
__device__ __forceinline__ void mma_tf32(float* c, const uint32_t* a,
                                         uint32_t b0, uint32_t b1) {
    asm volatile(
        "mma.sync.aligned.m16n8k8.row.col.f32.tf32.tf32.f32 "
        "{%0,%1,%2,%3}, {%4,%5,%6,%7}, {%8,%9}, {%0,%1,%2,%3};"
        : "+f"(c[0]), "+f"(c[1]), "+f"(c[2]), "+f"(c[3])
        : "r"(a[0]), "r"(a[1]), "r"(a[2]), "r"(a[3]), "r"(b0), "r"(b1));
}

// ---------------- CSR build --------------------------------------------------
__global__ void zero_cursor_kernel() {
    int i = blockIdx.x * blockDim.x + threadIdx.x;
    if (i < NN) g_cursor[i] = 0;
}

__global__ void hist_kernel(const int* __restrict__ ei) {
    int e = blockIdx.x * blockDim.x + threadIdx.x;
    if (e < NE) {
        int dst = ei[NE + e];
        if ((unsigned)dst < NN) atomicAdd(&g_cursor[dst], 1);
    }
}

__global__ void scan_kernel() {
    __shared__ int s[1024];
    __shared__ int carry;
    int tid = threadIdx.x;
    if (tid == 0) carry = 0;
    __syncthreads();
    for (int base = 0; base < NN; base += 1024) {
        int i = base + tid;
        int v = (i < NN) ? g_cursor[i] : 0;
        s[tid] = v;
        __syncthreads();
        #pragma unroll
        for (int off = 1; off < 1024; off <<= 1) {
            int t = (tid >= off) ? s[tid - off] : 0;
            __syncthreads();
            s[tid] += t;
            __syncthreads();
        }
        int incl = s[tid];
        int c = carry;
        if (i < NN) g_rowptr[i] = c + incl - v;
        __syncthreads();
        if (tid == 1023) carry = c + incl;
        __syncthreads();
    }
    if (tid == 0) g_rowptr[NN] = carry;
}

__global__ void fill_kernel(const int* __restrict__ ei) {
    int e = blockIdx.x * blockDim.x + threadIdx.x;
    if (e < NE) {
        int src = ei[e];
        int dst = ei[NE + e];
        if ((unsigned)dst < NN && (unsigned)src < NN) {
            int pos = atomicAdd(&g_cursor[dst], 1);
            g_col[g_rowptr[dst] + pos] = src;
        }
    }
}

// ---------------- weight prep: WT[l][n][k] = tf32(W[l][k][n]) ----------------
__global__ void prep_wt_kernel(const float* __restrict__ wr1, const float* __restrict__ wo1,
                               const float* __restrict__ wr2, const float* __restrict__ wo2,
                               const float* __restrict__ wr3, const float* __restrict__ wo3) {
    int i = blockIdx.x * blockDim.x + threadIdx.x;   // over 3*128*256
    if (i >= 3 * 128 * 256) return;
    int l = i >> 15;
    int r = i & 32767;
    int n = r >> 8;
    int k = r & 255;
    const float* wr = (l == 0) ? wr1 : (l == 1 ? wr2 : wr3);
    const float* wo = (l == 0) ? wo1 : (l == 1 ? wo2 : wo3);
    float v = (k < 128) ? wr[k * 128 + n] : wo[(k - 128) * 128 + n];
    g_wt[i] = tf32_rna(v);
}

// ---------------- aggregation: one warp per node, float4 lanes, 4x unroll ----
__global__ void agg_kernel(const float* __restrict__ xin, int which) {
    int gw   = (blockIdx.x * blockDim.x + threadIdx.x) >> 5;
    int lane = threadIdx.x & 31;
    if (gw >= NN) return;
    const float* h = (which == 0) ? xin : (which == 1 ? g_h1 : g_h2);
    int beg = g_rowptr[gw];
    int end = g_rowptr[gw + 1];
    const float4* hv = (const float4*)h;
    float4 acc = make_float4(0.f, 0.f, 0.f, 0.f);
    int j = beg;
    for (; j + 4 <= end; j += 4) {
        int s0 = g_col[j], s1 = g_col[j + 1], s2 = g_col[j + 2], s3 = g_col[j + 3];
        float4 v0 = hv[(size_t)s0 * 32 + lane];
        float4 v1 = hv[(size_t)s1 * 32 + lane];
        float4 v2 = hv[(size_t)s2 * 32 + lane];
        float4 v3 = hv[(size_t)s3 * 32 + lane];
        acc.x += v0.x + v1.x + v2.x + v3.x;
        acc.y += v0.y + v1.y + v2.y + v3.y;
        acc.z += v0.z + v1.z + v2.z + v3.z;
        acc.w += v0.w + v1.w + v2.w + v3.w;
    }
    for (; j < end; j++) {
        int s = g_col[j];
        float4 v = hv[(size_t)s * 32 + lane];
        acc.x += v.x; acc.y += v.y; acc.z += v.z; acc.w += v.w;
    }
    ((float4*)g_agg)[(size_t)gw * 32 + lane] = acc;
}

// ---------------- TF32 mma.sync GEMM: out = act([g_agg|h] @ WT^T + b) --------
// 128x128 tile, K=256 in 8 chunks of 32. 256 threads = 8 warps (4 M x 2 N),
// warp tile 32(M) x 64(N) = 2x8 m16n8k8 tiles, 64 fp32 acc/thread.
// SMEM holds fragment-major staged operands (conflict-free lds.v4 / lds.v2).
//   sA[((ks*8 + mt)*32 + tid)*4 + j]  (mt = row>>4 of 128 rows; 16KB)
//   sB[((ks*16 + nt)*32 + tid)*2 + j] (nt = n>>3  of 128 cols; 16KB)
template <bool RELU>
__global__ void __launch_bounds__(256, 2)
gemm_mma_kernel(const float* __restrict__ xin, int which, int layer,
                const float* __restrict__ bias,
                float* __restrict__ outarg, int outsel)
{
    __shared__ float sA[4096];
    __shared__ float sB[4096];

    const float* A1  = (which == 0) ? xin : (which == 1 ? g_h1 : g_h2);
    float*       out = (outsel == 0) ? g_h1 : (outsel == 1 ? g_h2 : outarg);
    const float* wt  = &g_wt[layer * 128 * 256];

    const int tid  = threadIdx.x;
    const int lane = tid & 31;
    const int wid  = tid >> 5;
    const int wm   = wid & 3;     // 0..3  -> M
    const int wn   = wid >> 2;    // 0..1  -> N
    const int m0   = blockIdx.x * 128;

    float acc[2][8][4];
    #pragma unroll
    for (int i = 0; i < 2; i++)
        #pragma unroll
        for (int j = 0; j < 8; j++)
            #pragma unroll
            for (int k = 0; k < 4; k++) acc[i][j][k] = 0.f;

    #pragma unroll 1
    for (int c = 0; c < 8; c++) {
        __syncthreads();   // protect previous chunk's smem reads

        // ---- stage A chunk (fragment-major, tf32-converted) ----
        {
            const float* A    = (c < 4) ? g_agg : A1;
            const int    kbase = (c & 3) * 32;
            #pragma unroll
            for (int it = 0; it < 4; it++) {
                int fidx = it * 256 + tid;       // 1024 float4s
                int r  = fidx >> 3;
                int cq = fidx & 7;
                float4 v = make_float4(0.f, 0.f, 0.f, 0.f);
                if (m0 + r < NN)
                    v = *(const float4*)&A[(size_t)(m0 + r) * 128 + kbase + cq * 4];
                int mt = r >> 4, rr = r & 15, g = rr & 7, jo = rr >> 3;
                int ks = cq >> 1;
                int j  = jo + ((cq & 1) << 1);
                int base = (ks * 8 + mt) * 128 + g * 16 + j;
                sA[base +  0] = tf32_rna(v.x);
                sA[base +  4] = tf32_rna(v.y);
                sA[base +  8] = tf32_rna(v.z);
                sA[base + 12] = tf32_rna(v.w);
            }
        }
        // ---- stage B chunk (fragment-major; wt already tf32) ----
        {
            const int kbase = c * 32;
            #pragma unroll
            for (int it = 0; it < 4; it++) {
                int fidx = it * 256 + tid;
                int n  = fidx >> 3;
                int cq = fidx & 7;
                float4 v = *(const float4*)&wt[(size_t)n * 256 + kbase + cq * 4];
                int nt = n >> 3, g = n & 7;
                int ks = cq >> 1;
                int j  = cq & 1;
                int base = (ks * 16 + nt) * 64 + g * 8 + j;
                sB[base + 0] = v.x;
                sB[base + 2] = v.y;
                sB[base + 4] = v.z;
                sB[base + 6] = v.w;
            }
        }
        __syncthreads();

        // ---- compute: 4 ksteps x (2 M-tiles x 8 N-tiles) mma ----
        #pragma unroll
        for (int ks = 0; ks < 4; ks++) {
            uint32_t a[2][4];
            #pragma unroll
            for (int mtl = 0; mtl < 2; mtl++) {
                int mt = wm * 2 + mtl;
                float4 af = *(const float4*)&sA[((ks * 8 + mt) * 32 + lane) * 4];
                a[mtl][0] = __float_as_uint(af.x);
                a[mtl][1] = __float_as_uint(af.y);
                a[mtl][2] = __float_as_uint(af.z);
                a[mtl][3] = __float_as_uint(af.w);
            }
            #pragma unroll
            for (int ntl = 0; ntl < 8; ntl++) {
                int nt = wn * 8 + ntl;
                float2 bf = *(const float2*)&sB[((ks * 16 + nt) * 32 + lane) * 2];
                uint32_t b0 = __float_as_uint(bf.x);
                uint32_t b1 = __float_as_uint(bf.y);
                mma_tf32(acc[0][ntl], a[0], b0, b1);
                mma_tf32(acc[1][ntl], a[1], b0, b1);
            }
        }
    }

    // ---- epilogue: bias + optional relu, float2 stores ----
    const int g   = lane >> 2;
    const int tig = lane & 3;
    #pragma unroll
    for (int mtl = 0; mtl < 2; mtl++) {
        #pragma unroll
        for (int h = 0; h < 2; h++) {
            int row = m0 + wm * 32 + mtl * 16 + h * 8 + g;
            if (row >= NN) continue;
            #pragma unroll
            for (int ntl = 0; ntl < 8; ntl++) {
                int col = wn * 64 + ntl * 8 + tig * 2;
                float2 o;
                o.x = acc[mtl][ntl][h * 2 + 0] + __ldg(&bias[col + 0]);
                o.y = acc[mtl][ntl][h * 2 + 1] + __ldg(&bias[col + 1]);
                if (RELU) { o.x = fmaxf(o.x, 0.f); o.y = fmaxf(o.y, 0.f); }
                *(float2*)&out[(size_t)row * 128 + col] = o;
            }
        }
    }
}

// ---------------- launch ------------------------------------------------------
extern "C" void kernel_launch(void* const* d_in, const int* in_sizes, int n_in,
                              void* d_out, int out_size) {
    const float* x       = (const float*)d_in[0];
    const int*   ei      = (const int*)d_in[1];
    const float* w_rel1  = (const float*)d_in[2];
    const float* w_root1 = (const float*)d_in[3];
    const float* b1      = (const float*)d_in[4];
    const float* w_rel2  = (const float*)d_in[5];
    const float* w_root2 = (const float*)d_in[6];
    const float* b2      = (const float*)d_in[7];
    const float* w_rel3  = (const float*)d_in[8];
    const float* w_root3 = (const float*)d_in[9];
    const float* b3      = (const float*)d_in[10];
    float*       out     = (float*)d_out;

    const int ZB = (NN + 255) / 256;
    const int EB = (NE + 255) / 256;
    const int AB = ((NN * 32) + 255) / 256;
    const int GB = (NN + 127) / 128;            // 782

    // CSR build + weight prep
    zero_cursor_kernel<<<ZB, 256>>>();
    hist_kernel<<<EB, 256>>>(ei);
    prep_wt_kernel<<<384, 256>>>(w_rel1, w_root1, w_rel2, w_root2, w_rel3, w_root3);
    scan_kernel<<<1, 1024>>>();
    zero_cursor_kernel<<<ZB, 256>>>();
    fill_kernel<<<EB, 256>>>(ei);

    // layer 1
    agg_kernel<<<AB, 256>>>(x, 0);
    gemm_mma_kernel<true><<<GB, 256>>>(x, 0, 0, b1, nullptr, 0);
    // layer 2
    agg_kernel<<<AB, 256>>>(x, 1);
    gemm_mma_kernel<true><<<GB, 256>>>(x, 1, 1, b2, nullptr, 1);
    // layer 3 (no relu) -> d_out
    agg_kernel<<<AB, 256>>>(x, 2);
    gemm_mma_kernel<false><<<GB, 256>>>(x, 2, 2, b3, out, 2);
}

// round 6
// speedup vs baseline: 1.9774x; 1.2718x over previous
#include <cuda_runtime.h>
#include <cstdint>

#define NN 100000
#define NE 1600000
#define D  128
#define SCAN_BLOCKS 98   // ceil(NN / 1024)

// ---------------- scratch (device globals — no allocation allowed) ----------
__device__ __align__(16) int   g_cursor[NN];
__device__ __align__(16) int   g_rowptr[NN + 1];
__device__ __align__(16) int   g_blocksum[SCAN_BLOCKS];
__device__ __align__(16) int   g_col[NE];
__device__ __align__(16) float g_agg[(size_t)NN * D];
__device__ __align__(16) float g_h1 [(size_t)NN * D];
__device__ __align__(16) float g_h2 [(size_t)NN * D];
// pre-transposed tf32-rounded weights: WT[layer][n=128][k=256] = [w_rel;w_root]^T
__device__ __align__(16) float g_wt [3 * 128 * 256];

__device__ __forceinline__ float tf32_rna(float x) {
    float r; asm("cvt.rna.tf32.f32 %0, %1;" : "=f"(r) : "f"(x)); return r;
}

// warp-level tensor-core mma (baseline PTX, works on compute_103)
__device__ __forceinline__ void mma_tf32(float* c, const uint32_t* a,
                                         uint32_t b0, uint32_t b1) {
    asm volatile(
        "mma.sync.aligned.m16n8k8.row.col.f32.tf32.tf32.f32 "
        "{%0,%1,%2,%3}, {%4,%5,%6,%7}, {%8,%9}, {%0,%1,%2,%3};"
        : "+f"(c[0]), "+f"(c[1]), "+f"(c[2]), "+f"(c[3])
        : "r"(a[0]), "r"(a[1]), "r"(a[2]), "r"(a[3]), "r"(b0), "r"(b1));
}

// ---------------- CSR build --------------------------------------------------
__global__ void zero_cursor_kernel() {
    int i = blockIdx.x * blockDim.x + threadIdx.x;
    if (i < NN) g_cursor[i] = 0;
}

__global__ void hist_kernel(const int* __restrict__ ei) {
    int e = blockIdx.x * blockDim.x + threadIdx.x;
    if (e < NE) {
        int dst = ei[NE + e];
        if ((unsigned)dst < NN) atomicAdd(&g_cursor[dst], 1);
    }
}

// ---- 3-pass parallel exclusive scan of g_cursor -> g_rowptr ----
__global__ void scan1_kernel() {
    const int tid  = threadIdx.x;
    const int lane = tid & 31;
    const int warp = tid >> 5;
    const int i    = blockIdx.x * 1024 + tid;
    int v = (i < NN) ? g_cursor[i] : 0;
    // inclusive warp scan
    int x = v;
    #pragma unroll
    for (int off = 1; off < 32; off <<= 1) {
        int t = __shfl_up_sync(0xFFFFFFFFu, x, off);
        if (lane >= off) x += t;
    }
    __shared__ int wsum[32];
    if (lane == 31) wsum[warp] = x;
    __syncthreads();
    if (warp == 0) {
        int y = wsum[lane];
        #pragma unroll
        for (int off = 1; off < 32; off <<= 1) {
            int t = __shfl_up_sync(0xFFFFFFFFu, y, off);
            if (lane >= off) y += t;
        }
        wsum[lane] = y;
    }
    __syncthreads();
    int blockExcl = (warp > 0) ? wsum[warp - 1] : 0;
    if (i < NN) g_rowptr[i] = blockExcl + x - v;   // exclusive prefix (local)
    if (tid == 1023) g_blocksum[blockIdx.x] = blockExcl + x;
}

__global__ void scan2_kernel() {   // 1 block, 128 threads
    __shared__ int s[128];
    int tid = threadIdx.x;
    int v = (tid < SCAN_BLOCKS) ? g_blocksum[tid] : 0;
    s[tid] = v;
    __syncthreads();
    #pragma unroll
    for (int off = 1; off < 128; off <<= 1) {
        int t = (tid >= off) ? s[tid - off] : 0;
        __syncthreads();
        s[tid] += t;
        __syncthreads();
    }
    if (tid < SCAN_BLOCKS) g_blocksum[tid] = s[tid] - v;  // exclusive
    if (tid == SCAN_BLOCKS - 1) g_rowptr[NN] = s[tid];
}

__global__ void scan3_kernel() {
    int i = blockIdx.x * 1024 + threadIdx.x;
    if (i < NN) g_rowptr[i] += g_blocksum[blockIdx.x];
}

__global__ void fill_kernel(const int* __restrict__ ei) {
    int e = blockIdx.x * blockDim.x + threadIdx.x;
    if (e < NE) {
        int src = ei[e];
        int dst = ei[NE + e];
        if ((unsigned)dst < NN && (unsigned)src < NN) {
            int pos = atomicAdd(&g_cursor[dst], 1);
            g_col[g_rowptr[dst] + pos] = src;
        }
    }
}

// ---------------- weight prep: WT[l][n][k] = tf32(W[l][k][n]) ----------------
__global__ void prep_wt_kernel(const float* __restrict__ wr1, const float* __restrict__ wo1,
                               const float* __restrict__ wr2, const float* __restrict__ wo2,
                               const float* __restrict__ wr3, const float* __restrict__ wo3) {
    int i = blockIdx.x * blockDim.x + threadIdx.x;   // over 3*128*256
    if (i >= 3 * 128 * 256) return;
    int l = i >> 15;
    int r = i & 32767;
    int n = r >> 8;
    int k = r & 255;
    const float* wr = (l == 0) ? wr1 : (l == 1 ? wr2 : wr3);
    const float* wo = (l == 0) ? wo1 : (l == 1 ? wo2 : wo3);
    float v = (k < 128) ? wr[k * 128 + n] : wo[(k - 128) * 128 + n];
    g_wt[i] = tf32_rna(v);
}

// ---------------- aggregation: one warp per node, float4 lanes, 4x unroll ----
__global__ void agg_kernel(const float* __restrict__ xin, int which) {
    int gw   = (blockIdx.x * blockDim.x + threadIdx.x) >> 5;
    int lane = threadIdx.x & 31;
    if (gw >= NN) return;
    const float* h = (which == 0) ? xin : (which == 1 ? g_h1 : g_h2);
    int beg = g_rowptr[gw];
    int end = g_rowptr[gw + 1];
    const float4* hv = (const float4*)h;
    float4 acc = make_float4(0.f, 0.f, 0.f, 0.f);
    int j = beg;
    for (; j + 4 <= end; j += 4) {
        int s0 = g_col[j], s1 = g_col[j + 1], s2 = g_col[j + 2], s3 = g_col[j + 3];
        float4 v0 = hv[(size_t)s0 * 32 + lane];
        float4 v1 = hv[(size_t)s1 * 32 + lane];
        float4 v2 = hv[(size_t)s2 * 32 + lane];
        float4 v3 = hv[(size_t)s3 * 32 + lane];
        acc.x += v0.x + v1.x + v2.x + v3.x;
        acc.y += v0.y + v1.y + v2.y + v3.y;
        acc.z += v0.z + v1.z + v2.z + v3.z;
        acc.w += v0.w + v1.w + v2.w + v3.w;
    }
    for (; j < end; j++) {
        int s = g_col[j];
        float4 v = hv[(size_t)s * 32 + lane];
        acc.x += v.x; acc.y += v.y; acc.z += v.z; acc.w += v.w;
    }
    ((float4*)g_agg)[(size_t)gw * 32 + lane] = acc;
}

// ---------------- TF32 mma.sync GEMM: out = act([g_agg|h] @ WT^T + b) --------
// 128x128 tile, K=256 in 8 chunks of 32. 256 threads = 8 warps (4 M x 2 N),
// warp tile 32(M) x 64(N) = 2x8 m16n8k8 tiles, 64 fp32 acc/thread.
template <bool RELU>
__global__ void __launch_bounds__(256, 2)
gemm_mma_kernel(const float* __restrict__ xin, int which, int layer,
                const float* __restrict__ bias,
                float* __restrict__ outarg, int outsel)
{
    __shared__ float sA[4096];
    __shared__ float sB[4096];

    const float* A1  = (which == 0) ? xin : (which == 1 ? g_h1 : g_h2);
    float*       out = (outsel == 0) ? g_h1 : (outsel == 1 ? g_h2 : outarg);
    const float* wt  = &g_wt[layer * 128 * 256];

    const int tid  = threadIdx.x;
    const int lane = tid & 31;
    const int wid  = tid >> 5;
    const int wm   = wid & 3;     // 0..3  -> M
    const int wn   = wid >> 2;    // 0..1  -> N
    const int m0   = blockIdx.x * 128;

    float acc[2][8][4];
    #pragma unroll
    for (int i = 0; i < 2; i++)
        #pragma unroll
        for (int j = 0; j < 8; j++)
            #pragma unroll
            for (int k = 0; k < 4; k++) acc[i][j][k] = 0.f;

    #pragma unroll 1
    for (int c = 0; c < 8; c++) {
        __syncthreads();

        // ---- stage A chunk (fragment-major, tf32-converted) ----
        {
            const float* A    = (c < 4) ? g_agg : A1;
            const int    kbase = (c & 3) * 32;
            #pragma unroll
            for (int it = 0; it < 4; it++) {
                int fidx = it * 256 + tid;
                int r  = fidx >> 3;
                int cq = fidx & 7;
                float4 v = make_float4(0.f, 0.f, 0.f, 0.f);
                if (m0 + r < NN)
                    v = *(const float4*)&A[(size_t)(m0 + r) * 128 + kbase + cq * 4];
                int mt = r >> 4, rr = r & 15, g = rr & 7, jo = rr >> 3;
                int ks = cq >> 1;
                int j  = jo + ((cq & 1) << 1);
                int base = (ks * 8 + mt) * 128 + g * 16 + j;
                sA[base +  0] = tf32_rna(v.x);
                sA[base +  4] = tf32_rna(v.y);
                sA[base +  8] = tf32_rna(v.z);
                sA[base + 12] = tf32_rna(v.w);
            }
        }
        // ---- stage B chunk (fragment-major; wt already tf32) ----
        {
            const int kbase = c * 32;
            #pragma unroll
            for (int it = 0; it < 4; it++) {
                int fidx = it * 256 + tid;
                int n  = fidx >> 3;
                int cq = fidx & 7;
                float4 v = *(const float4*)&wt[(size_t)n * 256 + kbase + cq * 4];
                int nt = n >> 3, g = n & 7;
                int ks = cq >> 1;
                int j  = cq & 1;
                int base = (ks * 16 + nt) * 64 + g * 8 + j;
                sB[base + 0] = v.x;
                sB[base + 2] = v.y;
                sB[base + 4] = v.z;
                sB[base + 6] = v.w;
            }
        }
        __syncthreads();

        // ---- compute: 4 ksteps x (2 M-tiles x 8 N-tiles) mma ----
        #pragma unroll
        for (int ks = 0; ks < 4; ks++) {
            uint32_t a[2][4];
            #pragma unroll
            for (int mtl = 0; mtl < 2; mtl++) {
                int mt = wm * 2 + mtl;
                float4 af = *(const float4*)&sA[((ks * 8 + mt) * 32 + lane) * 4];
                a[mtl][0] = __float_as_uint(af.x);
                a[mtl][1] = __float_as_uint(af.y);
                a[mtl][2] = __float_as_uint(af.z);
                a[mtl][3] = __float_as_uint(af.w);
            }
            #pragma unroll
            for (int ntl = 0; ntl < 8; ntl++) {
                int nt = wn * 8 + ntl;
                float2 bf = *(const float2*)&sB[((ks * 16 + nt) * 32 + lane) * 2];
                uint32_t b0 = __float_as_uint(bf.x);
                uint32_t b1 = __float_as_uint(bf.y);
                mma_tf32(acc[0][ntl], a[0], b0, b1);
                mma_tf32(acc[1][ntl], a[1], b0, b1);
            }
        }
    }

    // ---- epilogue: bias + optional relu, float2 stores ----
    const int g   = lane >> 2;
    const int tig = lane & 3;
    #pragma unroll
    for (int mtl = 0; mtl < 2; mtl++) {
        #pragma unroll
        for (int h = 0; h < 2; h++) {
            int row = m0 + wm * 32 + mtl * 16 + h * 8 + g;
            if (row >= NN) continue;
            #pragma unroll
            for (int ntl = 0; ntl < 8; ntl++) {
                int col = wn * 64 + ntl * 8 + tig * 2;
                float2 o;
                o.x = acc[mtl][ntl][h * 2 + 0] + __ldg(&bias[col + 0]);
                o.y = acc[mtl][ntl][h * 2 + 1] + __ldg(&bias[col + 1]);
                if (RELU) { o.x = fmaxf(o.x, 0.f); o.y = fmaxf(o.y, 0.f); }
                *(float2*)&out[(size_t)row * 128 + col] = o;
            }
        }
    }
}

// ---------------- launch ------------------------------------------------------
extern "C" void kernel_launch(void* const* d_in, const int* in_sizes, int n_in,
                              void* d_out, int out_size) {
    const float* x       = (const float*)d_in[0];
    const int*   ei      = (const int*)d_in[1];
    const float* w_rel1  = (const float*)d_in[2];
    const float* w_root1 = (const float*)d_in[3];
    const float* b1      = (const float*)d_in[4];
    const float* w_rel2  = (const float*)d_in[5];
    const float* w_root2 = (const float*)d_in[6];
    const float* b2      = (const float*)d_in[7];
    const float* w_rel3  = (const float*)d_in[8];
    const float* w_root3 = (const float*)d_in[9];
    const float* b3      = (const float*)d_in[10];
    float*       out     = (float*)d_out;

    const int ZB = (NN + 255) / 256;
    const int EB = (NE + 255) / 256;
    const int AB = ((NN * 32) + 255) / 256;
    const int GB = (NN + 127) / 128;            // 782

    // CSR build + weight prep
    zero_cursor_kernel<<<ZB, 256>>>();
    hist_kernel<<<EB, 256>>>(ei);
    prep_wt_kernel<<<384, 256>>>(w_rel1, w_root1, w_rel2, w_root2, w_rel3, w_root3);
    scan1_kernel<<<SCAN_BLOCKS, 1024>>>();
    scan2_kernel<<<1, 128>>>();
    scan3_kernel<<<SCAN_BLOCKS, 1024>>>();
    zero_cursor_kernel<<<ZB, 256>>>();
    fill_kernel<<<EB, 256>>>(ei);

    // layer 1
    agg_kernel<<<AB, 256>>>(x, 0);
    gemm_mma_kernel<true><<<GB, 256>>>(x, 0, 0, b1, nullptr, 0);
    // layer 2
    agg_kernel<<<AB, 256>>>(x, 1);
    gemm_mma_kernel<true><<<GB, 256>>>(x, 1, 1, b2, nullptr, 1);
    // layer 3 (no relu) -> d_out
    agg_kernel<<<AB, 256>>>(x, 2);
    gemm_mma_kernel<false><<<GB, 256>>>(x, 2, 2, b3, out, 2);
}